// round 16
// baseline (speedup 1.0000x reference)
#include <cuda_runtime.h>
#include <math.h>

// Shapes fixed by the reference: B=4, M=64, K=32, C=256 ; tiles = 256
//   g_v    [256][64]   per-tile (mu[32], diag_corr[32])   diag_corr_i = E_ii/512
//   g_c1t  [64][512]   reduced W1: rows 0..31 = 0.5*A1+B1 (k=i), rows 32..63 = -W1[o,i*33]
//   g_hpre [256][512]  pre-gelu hidden
//   g_h    [256][512]  gelu(h_pre)
//   g_ep   [16][256][1024] split-K partials of W2 @ h (sigmoid in k_attn)
// Output buffer = out (B,M,K,C) followed by adj (B,M,K,K).

__device__ float g_v   [256*64];
__device__ float g_c1t [64*512];
__device__ float g_hpre[256*512];
__device__ float g_h   [256*512];
__device__ float g_ep  [16*256*1024];

// sparse off-diagonal equality corrections (float collisions; usually none)
#define MAXFIX 2048
__device__ int   g_fixcnt;
__device__ int   g_fix_col[MAXFIX];
__device__ int   g_fix_ij [MAXFIX];
__device__ float g_fix_val[MAXFIX];

#define NEGBIG -9000000000000000.0f

__global__ void k_zero() { g_fixcnt = 0; }

// ---------------------------------------------------------------------------
// Kernel 1 (512 thr): per-tile stats -> adj, and (mu, diag corr) -> g_v.
// Off-diagonal exact-equality hits are appended to the fix list.
// ---------------------------------------------------------------------------
__global__ __launch_bounds__(512) void k_stats(const float* __restrict__ x,
                                               float* __restrict__ adj) {
    __shared__ float xs[32*257];
    __shared__ float mu[32];
    __shared__ float rs[32];
    const int tile = blockIdx.x;
    const int tid  = threadIdx.x;
    const float* xt = x + (size_t)tile * 8192;

    for (int idx = tid; idx < 8192; idx += 512)
        xs[(idx >> 8)*257 + (idx & 255)] = xt[idx];
    __syncthreads();

    {   // row sums + sumsq: 16 threads per row
        int r = tid >> 4, g = tid & 15;
        const float* row = xs + r*257 + g*16;
        float s = 0.f, s2 = 0.f;
        #pragma unroll
        for (int c = 0; c < 16; ++c) { float v = row[c]; s += v; s2 = fmaf(v, v, s2); }
        #pragma unroll
        for (int off = 8; off; off >>= 1) {
            s  += __shfl_down_sync(0xffffffffu, s,  off, 16);
            s2 += __shfl_down_sync(0xffffffffu, s2, off, 16);
        }
        if (g == 0) {
            float m = s * (1.0f/256.0f);
            mu[r] = m;
            rs[r] = 1.0f / sqrtf(s2 - 256.0f*m*m);
        }
    }
    __syncthreads();

    if (tid < 32) g_v[tile*64 + tid] = mu[tid];

    // pair loop: lane = j; each thread handles i in {w, w+16}
    const int w = tid >> 5, lane = tid & 31;
    const float* rowj = xs + lane*257;
    const float muj = mu[lane];
    const float rsj = rs[lane];

    float sab[2] = {0.f,0.f};
    float eqs[2] = {0.f,0.f};
    #pragma unroll 8
    for (int c = 0; c < 256; ++c) {
        float b = rowj[c];
        #pragma unroll
        for (int k = 0; k < 2; ++k) {
            float a = xs[(k*16 + w)*257 + c];
            sab[k] = fmaf(a, b, sab[k]);
            if (a == b) eqs[k] += b;            // exact equality (pos mask)
        }
    }
    #pragma unroll
    for (int k = 0; k < 2; ++k) {
        int i = k*16 + w;
        float mui = mu[i];
        float covraw = sab[k] - 256.0f*mui*muj;
        int o = i*32 + lane;
        adj[(size_t)tile*1024 + o] = covraw * rs[i] * rsj;
        if (lane == i) {
            g_v[tile*64 + 32 + i] = eqs[k] * (1.0f/512.0f);
        } else if (eqs[k] != 0.0f) {            // rare float collision
            int slot = atomicAdd(&g_fixcnt, 1);
            if (slot < MAXFIX) {
                g_fix_col[slot] = tile;
                g_fix_ij [slot] = o;
                g_fix_val[slot] = -eqs[k] * (1.0f/512.0f);
            }
        }
    }
}

// ---------------------------------------------------------------------------
// W1 reduction: C1[o,i] = 0.5*sum_j W1[o,i*32+j] + sum_i' W1[o,i'*32+i]
// stored transposed g_c1t[k][o]; rows 32..63 hold -W1[o,i*33] (diag weights).
// One warp per o.
// ---------------------------------------------------------------------------
__global__ __launch_bounds__(128) void k_w1red(const float* __restrict__ W1) {
    const int o = blockIdx.x*4 + (threadIdx.x >> 5);
    const int lane = threadIdx.x & 31;
    const float* row = W1 + (size_t)o * 1024;
    float bacc = 0.f, areg = 0.f;
    #pragma unroll
    for (int i = 0; i < 32; ++i) {
        float wv = row[i*32 + lane];
        bacc += wv;
        float a = wv;
        #pragma unroll
        for (int off = 16; off; off >>= 1) a += __shfl_xor_sync(0xffffffffu, a, off);
        if (lane == i) areg = a;
    }
    g_c1t[lane*512 + o]      = 0.5f*areg + bacc;
    g_c1t[(32+lane)*512 + o] = -row[lane*33];
}

// ---------------------------------------------------------------------------
// GEMM1 (reduced, K=64): h_pre[col][o] = dot(g_c1t[:,o], g_v[col][:])
// One block per 8 cols, each thread handles o = tid and tid+256.
// ---------------------------------------------------------------------------
__global__ __launch_bounds__(256) void k_gemm1() {
    __shared__ float v[8][64];
    const int tid = threadIdx.x;
    const int b0 = blockIdx.x*8;
    for (int t = tid; t < 512; t += 256) v[t >> 6][t & 63] = g_v[b0*64 + t];
    __syncthreads();

    float acc[8][2];
    #pragma unroll
    for (int cc = 0; cc < 8; ++cc) { acc[cc][0] = 0.f; acc[cc][1] = 0.f; }
    #pragma unroll 8
    for (int k = 0; k < 64; ++k) {
        float c0 = g_c1t[k*512 + tid];
        float c1 = g_c1t[k*512 + tid + 256];
        #pragma unroll
        for (int cc = 0; cc < 8; ++cc) {
            float vv = v[cc][k];
            acc[cc][0] = fmaf(c0, vv, acc[cc][0]);
            acc[cc][1] = fmaf(c1, vv, acc[cc][1]);
        }
    }
    #pragma unroll
    for (int cc = 0; cc < 8; ++cc) {
        g_hpre[(size_t)(b0+cc)*512 + tid]       = acc[cc][0];
        g_hpre[(size_t)(b0+cc)*512 + tid + 256] = acc[cc][1];
    }
}

// ---------------------------------------------------------------------------
// Apply rare off-diagonal corrections (before gelu). Usually cnt==0.
// ---------------------------------------------------------------------------
__global__ __launch_bounds__(512) void k_fix(const float* __restrict__ W1) {
    int n = g_fixcnt; if (n > MAXFIX) n = MAXFIX;
    const int o = threadIdx.x;
    for (int e = 0; e < n; ++e) {
        int col = g_fix_col[e], ij = g_fix_ij[e];
        float val = g_fix_val[e];
        g_hpre[(size_t)col*512 + o] += W1[(size_t)o*1024 + ij] * val;
    }
}

// ---------------------------------------------------------------------------
// GELU (exact erf)
// ---------------------------------------------------------------------------
__device__ __forceinline__ float gelu_f(float v) {
    return 0.5f * v * (1.0f + erff(v * 0.70710678118654752f));
}
__global__ __launch_bounds__(256) void k_gelu() {
    int idx = blockIdx.x*256 + threadIdx.x;   // 32768 float4
    float4 a = ((const float4*)g_hpre)[idx];
    ((float4*)g_h)[idx] = make_float4(gelu_f(a.x), gelu_f(a.y), gelu_f(a.z), gelu_f(a.w));
}

// ---------------------------------------------------------------------------
// GEMM2 partials: tile 128(o) x 64(col), 256 thr, micro 8x4, split-K=16
// (K=32 per CTA). 6 LDG.128 up front, single barrier, 32 unrolled k-iters.
// OUT = g_ep[bz][col][1024].
// ---------------------------------------------------------------------------
__global__ __launch_bounds__(256) void k_gemm2(const float* __restrict__ W2) {
    __shared__ float Ws[32][132];
    __shared__ float Xs[32][68];
    const int tid = threadIdx.x;
    const int o0 = blockIdx.x*128, c0 = blockIdx.y*64;
    const int kbase = blockIdx.z * 32;
    const int to = tid & 15, tc = tid >> 4;   // o = o0+to*8+{0..7}, col = c0+tc*4+{0..3}
    const int lo = tid >> 3, lf = tid & 7;
    const int kk = lf*4;

    const float* wp = W2 + (size_t)(o0 + lo)*512 + kbase + lf*4;
    const float* xp = g_h + (size_t)(c0 + lo)*512 + kbase + lf*4;

    float4 w0 = *(const float4*)(wp);
    float4 w1 = *(const float4*)(wp + 32*512);
    float4 w2 = *(const float4*)(wp + 64*512);
    float4 w3 = *(const float4*)(wp + 96*512);
    float4 x0 = *(const float4*)(xp);
    float4 x1 = *(const float4*)(xp + 32*512);

    Ws[kk+0][lo]    = w0.x; Ws[kk+1][lo]    = w0.y; Ws[kk+2][lo]    = w0.z; Ws[kk+3][lo]    = w0.w;
    Ws[kk+0][lo+32] = w1.x; Ws[kk+1][lo+32] = w1.y; Ws[kk+2][lo+32] = w1.z; Ws[kk+3][lo+32] = w1.w;
    Ws[kk+0][lo+64] = w2.x; Ws[kk+1][lo+64] = w2.y; Ws[kk+2][lo+64] = w2.z; Ws[kk+3][lo+64] = w2.w;
    Ws[kk+0][lo+96] = w3.x; Ws[kk+1][lo+96] = w3.y; Ws[kk+2][lo+96] = w3.z; Ws[kk+3][lo+96] = w3.w;
    Xs[kk+0][lo]    = x0.x; Xs[kk+1][lo]    = x0.y; Xs[kk+2][lo]    = x0.z; Xs[kk+3][lo]    = x0.w;
    Xs[kk+0][lo+32] = x1.x; Xs[kk+1][lo+32] = x1.y; Xs[kk+2][lo+32] = x1.z; Xs[kk+3][lo+32] = x1.w;

    __syncthreads();   // only barrier

    float acc[8][4];
    #pragma unroll
    for (int i = 0; i < 8; ++i)
        #pragma unroll
        for (int j = 0; j < 4; ++j) acc[i][j] = 0.f;

    #pragma unroll
    for (int k2 = 0; k2 < 32; ++k2) {
        const float4 a0 = *(const float4*)&Ws[k2][to*8];
        const float4 a1 = *(const float4*)&Ws[k2][to*8 + 4];
        const float4 b  = *(const float4*)&Xs[k2][tc*4];
        acc[0][0]=fmaf(a0.x,b.x,acc[0][0]); acc[1][0]=fmaf(a0.y,b.x,acc[1][0]);
        acc[2][0]=fmaf(a0.z,b.x,acc[2][0]); acc[3][0]=fmaf(a0.w,b.x,acc[3][0]);
        acc[4][0]=fmaf(a1.x,b.x,acc[4][0]); acc[5][0]=fmaf(a1.y,b.x,acc[5][0]);
        acc[6][0]=fmaf(a1.z,b.x,acc[6][0]); acc[7][0]=fmaf(a1.w,b.x,acc[7][0]);
        acc[0][1]=fmaf(a0.x,b.y,acc[0][1]); acc[1][1]=fmaf(a0.y,b.y,acc[1][1]);
        acc[2][1]=fmaf(a0.z,b.y,acc[2][1]); acc[3][1]=fmaf(a0.w,b.y,acc[3][1]);
        acc[4][1]=fmaf(a1.x,b.y,acc[4][1]); acc[5][1]=fmaf(a1.y,b.y,acc[5][1]);
        acc[6][1]=fmaf(a1.z,b.y,acc[6][1]); acc[7][1]=fmaf(a1.w,b.y,acc[7][1]);
        acc[0][2]=fmaf(a0.x,b.z,acc[0][2]); acc[1][2]=fmaf(a0.y,b.z,acc[1][2]);
        acc[2][2]=fmaf(a0.z,b.z,acc[2][2]); acc[3][2]=fmaf(a0.w,b.z,acc[3][2]);
        acc[4][2]=fmaf(a1.x,b.z,acc[4][2]); acc[5][2]=fmaf(a1.y,b.z,acc[5][2]);
        acc[6][2]=fmaf(a1.z,b.z,acc[6][2]); acc[7][2]=fmaf(a1.w,b.z,acc[7][2]);
        acc[0][3]=fmaf(a0.x,b.w,acc[0][3]); acc[1][3]=fmaf(a0.y,b.w,acc[1][3]);
        acc[2][3]=fmaf(a0.z,b.w,acc[2][3]); acc[3][3]=fmaf(a0.w,b.w,acc[3][3]);
        acc[4][3]=fmaf(a1.x,b.w,acc[4][3]); acc[5][3]=fmaf(a1.y,b.w,acc[5][3]);
        acc[6][3]=fmaf(a1.z,b.w,acc[6][3]); acc[7][3]=fmaf(a1.w,b.w,acc[7][3]);
    }

    const int col = c0 + tc*4;
    const int o   = o0 + to*8;
    float* outp = g_ep + (size_t)blockIdx.z*(256*1024) + (size_t)col*1024 + o;
    #pragma unroll
    for (int j = 0; j < 4; ++j) {
        *(float4*)(outp + (size_t)j*1024)     = make_float4(acc[0][j], acc[1][j], acc[2][j], acc[3][j]);
        *(float4*)(outp + (size_t)j*1024 + 4) = make_float4(acc[4][j], acc[5][j], acc[6][j], acc[7][j]);
    }
}

// ---------------------------------------------------------------------------
// Kernel 4 (512 thr): combine 16 GEMM2 partials + sigmoid, masked softmax,
// then out = attn @ x (per tile)
// ---------------------------------------------------------------------------
__global__ __launch_bounds__(512) void k_attn(const float* __restrict__ x,
                                              const float* __restrict__ adj,
                                              float* __restrict__ out) {
    __shared__ float xs[32*257];
    __shared__ float at[32*36];     // at[j][i] = attn[i][j]
    const int tile = blockIdx.x;
    const int tid = threadIdx.x, w = tid >> 5, lane = tid & 31;
    const float* xt = x + (size_t)tile*8192;

    for (int idx = tid; idx < 8192; idx += 512)
        xs[(idx >> 8)*257 + (idx & 255)] = xt[idx];

    const float* e0 = g_ep + (size_t)tile*1024;
    const float* ar = adj + (size_t)tile*1024;
    #pragma unroll
    for (int k = 0; k < 2; ++k) {
        int i = k*16 + w;
        int o = i*32 + lane;
        float a = ar[o];
        float e = 0.f;
        #pragma unroll
        for (int t = 0; t < 16; ++t) e += e0[o + (size_t)t*256*1024];
        float v = (a > 0.f) ? 1.0f/(1.0f + expf(-e)) : NEGBIG;
        float mx = v;
        #pragma unroll
        for (int off = 16; off; off >>= 1) mx = fmaxf(mx, __shfl_xor_sync(0xffffffffu, mx, off));
        float pv = expf(v - mx);
        float s = pv;
        #pragma unroll
        for (int off = 16; off; off >>= 1) s += __shfl_xor_sync(0xffffffffu, s, off);
        at[lane*36 + i] = pv / s;
    }
    __syncthreads();

    const int c = tid & 255;
    const int half = tid >> 8;          // 0 or 1
    float acc[16];
    #pragma unroll
    for (int i = 0; i < 16; ++i) acc[i] = 0.f;
    for (int j = 0; j < 32; ++j) {
        float b = xs[j*257 + c];
        const float4* arow = (const float4*)(at + j*36 + half*16);
        #pragma unroll
        for (int q = 0; q < 4; ++q) {
            float4 aw = arow[q];
            acc[q*4+0] = fmaf(aw.x, b, acc[q*4+0]);
            acc[q*4+1] = fmaf(aw.y, b, acc[q*4+1]);
            acc[q*4+2] = fmaf(aw.z, b, acc[q*4+2]);
            acc[q*4+3] = fmaf(aw.w, b, acc[q*4+3]);
        }
    }
    float* orow = out + (size_t)tile*8192 + (half*16)*256 + c;
    #pragma unroll
    for (int i = 0; i < 16; ++i) orow[i*256] = acc[i];
}

// ---------------------------------------------------------------------------
extern "C" void kernel_launch(void* const* d_in, const int* in_sizes, int n_in,
                              void* d_out, int out_size) {
    const float* x  = (const float*)d_in[0];
    const float* W1 = (const float*)d_in[1];
    const float* W2 = (const float*)d_in[2];
    (void)n_in; (void)out_size;

    int B = in_sizes[0] / (64*32*256);     // = 4
    int tiles = B * 64;                    // = 256
    float* out = (float*)d_out;
    float* adj = out + (size_t)tiles * 8192;   // out first, then adj

    k_zero <<<1, 1>>>();
    k_stats<<<tiles, 512>>>(x, adj);
    k_w1red<<<128, 128>>>(W1);             // 512 o's, one warp each
    k_gemm1<<<tiles/8, 256>>>();
    k_fix  <<<1, 512>>>(W1);
    k_gelu <<<(tiles*512)/(4*256), 256>>>();
    k_gemm2<<<dim3(8, 4, 16), 256>>>(W2);  // 1024x256, K=512, split-K=16
    k_attn <<<tiles, 512>>>(x, adj, out);
}

// round 17
// speedup vs baseline: 1.2292x; 1.2292x over previous
#include <cuda_runtime.h>
#include <math.h>

// Shapes fixed by the reference: B=4, M=64, K=32, C=256 ; tiles = 256
//   g_c1t [64][512]  reduced W1: rows 0..31 = (0.5*A1+B1)[k][o], rows 32..63 = -W1[o,k*33]
//                    where A1[o,i]=sum_j W1[o,i*32+j], B1[o,j]=sum_i W1[o,i*32+j]
//   g_h   [256][512] gelu(h_pre), h_pre[col][o] = C1 . (mu, E_diag/512) + sparse fixes
//   g_ep  [16][256][1024] split-K partials of W2 @ h (sigmoid applied in k_attn)
// Output buffer = out (B,M,K,C) followed by adj (B,M,K,K).

__device__ float g_c1t[64*512];
__device__ float g_h  [256*512];
__device__ float g_ep [16*256*1024];

#define NEGBIG -9000000000000000.0f

// ---------------------------------------------------------------------------
// W1 reduction: c1t[i][o] = 0.5*sum_j W1[o,i*32+j] + sum_i' W1[o,i'*32+i]
// rows 32..63 hold -W1[o,i*33] (diagonal weights). One warp per o.
// ---------------------------------------------------------------------------
__global__ __launch_bounds__(128) void k_w1red(const float* __restrict__ W1) {
    const int o = blockIdx.x*4 + (threadIdx.x >> 5);
    const int lane = threadIdx.x & 31;
    const float* row = W1 + (size_t)o * 1024;
    float bacc = 0.f, areg = 0.f;
    #pragma unroll
    for (int i = 0; i < 32; ++i) {
        float wv = row[i*32 + lane];
        bacc += wv;
        float a = wv;
        #pragma unroll
        for (int off = 16; off; off >>= 1) a += __shfl_xor_sync(0xffffffffu, a, off);
        if (lane == i) areg = a;
    }
    g_c1t[lane*512 + o]      = 0.5f*areg + bacc;
    g_c1t[(32+lane)*512 + o] = -row[lane*33];
}

// ---------------------------------------------------------------------------
// GELU (exact erf)
// ---------------------------------------------------------------------------
__device__ __forceinline__ float gelu_f(float v) {
    return 0.5f * v * (1.0f + erff(v * 0.70710678118654752f));
}

// ---------------------------------------------------------------------------
// Fused kernel 1 (512 thr, one CTA per tile):
//   stats -> adj ; reduced GEMM1 (K=64) + local sparse collision fixes
//   + GELU -> g_h[tile][0..511]
// pooled_ij = 0.5*mu_i + mu_j - E_ij/512 ; E almost surely diagonal, so
// h_pre[o] = sum_k c1t[k][o]*mu_k + sum_k c1t[32+k][o]*(E_kk/512)
//            - sum_{offdiag hits} W1[o,ij]*E_ij/512
// ---------------------------------------------------------------------------
__global__ __launch_bounds__(512) void k_stats(const float* __restrict__ x,
                                               const float* __restrict__ W1,
                                               float* __restrict__ adj) {
    __shared__ float xs[32*257];
    __shared__ float mu[32];
    __shared__ float rs[32];
    __shared__ float dc[32];          // E_ii/512
    __shared__ int   nfix;
    __shared__ int   fij [64];
    __shared__ float fval[64];
    const int tile = blockIdx.x;
    const int tid  = threadIdx.x;
    const float* xt = x + (size_t)tile * 8192;

    if (tid == 0) nfix = 0;
    for (int idx = tid; idx < 8192; idx += 512)
        xs[(idx >> 8)*257 + (idx & 255)] = xt[idx];
    __syncthreads();

    {   // row sums + sumsq: 16 threads per row
        int r = tid >> 4, g = tid & 15;
        const float* row = xs + r*257 + g*16;
        float s = 0.f, s2 = 0.f;
        #pragma unroll
        for (int c = 0; c < 16; ++c) { float v = row[c]; s += v; s2 = fmaf(v, v, s2); }
        #pragma unroll
        for (int off = 8; off; off >>= 1) {
            s  += __shfl_down_sync(0xffffffffu, s,  off, 16);
            s2 += __shfl_down_sync(0xffffffffu, s2, off, 16);
        }
        if (g == 0) {
            float m = s * (1.0f/256.0f);
            mu[r] = m;
            rs[r] = 1.0f / sqrtf(s2 - 256.0f*m*m);
        }
    }
    __syncthreads();

    // pair loop: lane = j; each thread handles i in {w, w+16}
    const int w = tid >> 5, lane = tid & 31;
    const float* rowj = xs + lane*257;
    const float muj = mu[lane];
    const float rsj = rs[lane];

    float sab[2] = {0.f,0.f};
    float eqs[2] = {0.f,0.f};
    #pragma unroll 8
    for (int c = 0; c < 256; ++c) {
        float b = rowj[c];
        #pragma unroll
        for (int k = 0; k < 2; ++k) {
            float a = xs[(k*16 + w)*257 + c];
            sab[k] = fmaf(a, b, sab[k]);
            if (a == b) eqs[k] += b;            // exact equality (pos mask)
        }
    }
    #pragma unroll
    for (int k = 0; k < 2; ++k) {
        int i = k*16 + w;
        float mui = mu[i];
        float covraw = sab[k] - 256.0f*mui*muj;
        int o = i*32 + lane;
        adj[(size_t)tile*1024 + o] = covraw * rs[i] * rsj;
        if (lane == i) {
            dc[i] = eqs[k] * (1.0f/512.0f);
        } else if (eqs[k] != 0.0f) {            // rare float collision
            int slot = atomicAdd(&nfix, 1);
            if (slot < 64) {
                fij [slot] = o;
                fval[slot] = -eqs[k] * (1.0f/512.0f);
            }
        }
    }
    __syncthreads();

    // reduced GEMM1: o = tid, K=64 (32 mu-terms + 32 diag-terms)
    {
        const int o = tid;
        float acc = 0.f;
        #pragma unroll
        for (int k = 0; k < 32; ++k)
            acc = fmaf(g_c1t[k*512 + o], mu[k], acc);
        #pragma unroll
        for (int k = 0; k < 32; ++k)
            acc = fmaf(g_c1t[(32+k)*512 + o], dc[k], acc);
        int n = nfix; if (n > 64) n = 64;
        for (int e = 0; e < n; ++e)
            acc = fmaf(W1[(size_t)o*1024 + fij[e]], fval[e], acc);
        g_h[(size_t)tile*512 + o] = gelu_f(acc);
    }
}

// ---------------------------------------------------------------------------
// GEMM2 partials: tile 128(o) x 64(col), 256 thr, micro 8x4, split-K=16
// (K=32 per CTA). 6 LDG.128 up front, single barrier, 32 unrolled k-iters.
// OUT = g_ep[bz][col][1024].
// ---------------------------------------------------------------------------
__global__ __launch_bounds__(256) void k_gemm2(const float* __restrict__ W2) {
    __shared__ float Ws[32][132];
    __shared__ float Xs[32][68];
    const int tid = threadIdx.x;
    const int o0 = blockIdx.x*128, c0 = blockIdx.y*64;
    const int kbase = blockIdx.z * 32;
    const int to = tid & 15, tc = tid >> 4;   // o = o0+to*8+{0..7}, col = c0+tc*4+{0..3}
    const int lo = tid >> 3, lf = tid & 7;
    const int kk = lf*4;

    const float* wp = W2 + (size_t)(o0 + lo)*512 + kbase + lf*4;
    const float* xp = g_h + (size_t)(c0 + lo)*512 + kbase + lf*4;

    float4 w0 = *(const float4*)(wp);
    float4 w1 = *(const float4*)(wp + 32*512);
    float4 w2 = *(const float4*)(wp + 64*512);
    float4 w3 = *(const float4*)(wp + 96*512);
    float4 x0 = *(const float4*)(xp);
    float4 x1 = *(const float4*)(xp + 32*512);

    Ws[kk+0][lo]    = w0.x; Ws[kk+1][lo]    = w0.y; Ws[kk+2][lo]    = w0.z; Ws[kk+3][lo]    = w0.w;
    Ws[kk+0][lo+32] = w1.x; Ws[kk+1][lo+32] = w1.y; Ws[kk+2][lo+32] = w1.z; Ws[kk+3][lo+32] = w1.w;
    Ws[kk+0][lo+64] = w2.x; Ws[kk+1][lo+64] = w2.y; Ws[kk+2][lo+64] = w2.z; Ws[kk+3][lo+64] = w2.w;
    Ws[kk+0][lo+96] = w3.x; Ws[kk+1][lo+96] = w3.y; Ws[kk+2][lo+96] = w3.z; Ws[kk+3][lo+96] = w3.w;
    Xs[kk+0][lo]    = x0.x; Xs[kk+1][lo]    = x0.y; Xs[kk+2][lo]    = x0.z; Xs[kk+3][lo]    = x0.w;
    Xs[kk+0][lo+32] = x1.x; Xs[kk+1][lo+32] = x1.y; Xs[kk+2][lo+32] = x1.z; Xs[kk+3][lo+32] = x1.w;

    __syncthreads();   // only barrier

    float acc[8][4];
    #pragma unroll
    for (int i = 0; i < 8; ++i)
        #pragma unroll
        for (int j = 0; j < 4; ++j) acc[i][j] = 0.f;

    #pragma unroll
    for (int k2 = 0; k2 < 32; ++k2) {
        const float4 a0 = *(const float4*)&Ws[k2][to*8];
        const float4 a1 = *(const float4*)&Ws[k2][to*8 + 4];
        const float4 b  = *(const float4*)&Xs[k2][tc*4];
        acc[0][0]=fmaf(a0.x,b.x,acc[0][0]); acc[1][0]=fmaf(a0.y,b.x,acc[1][0]);
        acc[2][0]=fmaf(a0.z,b.x,acc[2][0]); acc[3][0]=fmaf(a0.w,b.x,acc[3][0]);
        acc[4][0]=fmaf(a1.x,b.x,acc[4][0]); acc[5][0]=fmaf(a1.y,b.x,acc[5][0]);
        acc[6][0]=fmaf(a1.z,b.x,acc[6][0]); acc[7][0]=fmaf(a1.w,b.x,acc[7][0]);
        acc[0][1]=fmaf(a0.x,b.y,acc[0][1]); acc[1][1]=fmaf(a0.y,b.y,acc[1][1]);
        acc[2][1]=fmaf(a0.z,b.y,acc[2][1]); acc[3][1]=fmaf(a0.w,b.y,acc[3][1]);
        acc[4][1]=fmaf(a1.x,b.y,acc[4][1]); acc[5][1]=fmaf(a1.y,b.y,acc[5][1]);
        acc[6][1]=fmaf(a1.z,b.y,acc[6][1]); acc[7][1]=fmaf(a1.w,b.y,acc[7][1]);
        acc[0][2]=fmaf(a0.x,b.z,acc[0][2]); acc[1][2]=fmaf(a0.y,b.z,acc[1][2]);
        acc[2][2]=fmaf(a0.z,b.z,acc[2][2]); acc[3][2]=fmaf(a0.w,b.z,acc[3][2]);
        acc[4][2]=fmaf(a1.x,b.z,acc[4][2]); acc[5][2]=fmaf(a1.y,b.z,acc[5][2]);
        acc[6][2]=fmaf(a1.z,b.z,acc[6][2]); acc[7][2]=fmaf(a1.w,b.z,acc[7][2]);
        acc[0][3]=fmaf(a0.x,b.w,acc[0][3]); acc[1][3]=fmaf(a0.y,b.w,acc[1][3]);
        acc[2][3]=fmaf(a0.z,b.w,acc[2][3]); acc[3][3]=fmaf(a0.w,b.w,acc[3][3]);
        acc[4][3]=fmaf(a1.x,b.w,acc[4][3]); acc[5][3]=fmaf(a1.y,b.w,acc[5][3]);
        acc[6][3]=fmaf(a1.z,b.w,acc[6][3]); acc[7][3]=fmaf(a1.w,b.w,acc[7][3]);
    }

    const int col = c0 + tc*4;
    const int o   = o0 + to*8;
    float* outp = g_ep + (size_t)blockIdx.z*(256*1024) + (size_t)col*1024 + o;
    #pragma unroll
    for (int j = 0; j < 4; ++j) {
        *(float4*)(outp + (size_t)j*1024)     = make_float4(acc[0][j], acc[1][j], acc[2][j], acc[3][j]);
        *(float4*)(outp + (size_t)j*1024 + 4) = make_float4(acc[4][j], acc[5][j], acc[6][j], acc[7][j]);
    }
}

// ---------------------------------------------------------------------------
// Kernel 3 (512 thr): combine 16 GEMM2 partials + sigmoid, masked softmax,
// then out = attn @ x (per tile)
// ---------------------------------------------------------------------------
__global__ __launch_bounds__(512) void k_attn(const float* __restrict__ x,
                                              const float* __restrict__ adj,
                                              float* __restrict__ out) {
    __shared__ float xs[32*257];
    __shared__ float at[32*36];     // at[j][i] = attn[i][j]
    const int tile = blockIdx.x;
    const int tid = threadIdx.x, w = tid >> 5, lane = tid & 31;
    const float* xt = x + (size_t)tile*8192;

    for (int idx = tid; idx < 8192; idx += 512)
        xs[(idx >> 8)*257 + (idx & 255)] = xt[idx];

    const float* e0 = g_ep + (size_t)tile*1024;
    const float* ar = adj + (size_t)tile*1024;
    #pragma unroll
    for (int k = 0; k < 2; ++k) {
        int i = k*16 + w;
        int o = i*32 + lane;
        float a = ar[o];
        float e = 0.f;
        #pragma unroll
        for (int t = 0; t < 16; ++t) e += e0[o + (size_t)t*256*1024];
        float v = (a > 0.f) ? 1.0f/(1.0f + expf(-e)) : NEGBIG;
        float mx = v;
        #pragma unroll
        for (int off = 16; off; off >>= 1) mx = fmaxf(mx, __shfl_xor_sync(0xffffffffu, mx, off));
        float pv = expf(v - mx);
        float s = pv;
        #pragma unroll
        for (int off = 16; off; off >>= 1) s += __shfl_xor_sync(0xffffffffu, s, off);
        at[lane*36 + i] = pv / s;
    }
    __syncthreads();

    const int c = tid & 255;
    const int half = tid >> 8;          // 0 or 1
    float acc[16];
    #pragma unroll
    for (int i = 0; i < 16; ++i) acc[i] = 0.f;
    for (int j = 0; j < 32; ++j) {
        float b = xs[j*257 + c];
        const float4* arow = (const float4*)(at + j*36 + half*16);
        #pragma unroll
        for (int q = 0; q < 4; ++q) {
            float4 aw = arow[q];
            acc[q*4+0] = fmaf(aw.x, b, acc[q*4+0]);
            acc[q*4+1] = fmaf(aw.y, b, acc[q*4+1]);
            acc[q*4+2] = fmaf(aw.z, b, acc[q*4+2]);
            acc[q*4+3] = fmaf(aw.w, b, acc[q*4+3]);
        }
    }
    float* orow = out + (size_t)tile*8192 + (half*16)*256 + c;
    #pragma unroll
    for (int i = 0; i < 16; ++i) orow[i*256] = acc[i];
}

// ---------------------------------------------------------------------------
extern "C" void kernel_launch(void* const* d_in, const int* in_sizes, int n_in,
                              void* d_out, int out_size) {
    const float* x  = (const float*)d_in[0];
    const float* W1 = (const float*)d_in[1];
    const float* W2 = (const float*)d_in[2];
    (void)n_in; (void)out_size;

    int B = in_sizes[0] / (64*32*256);     // = 4
    int tiles = B * 64;                    // = 256
    float* out = (float*)d_out;
    float* adj = out + (size_t)tiles * 8192;   // out first, then adj

    k_w1red<<<128, 128>>>(W1);             // 512 o's, one warp each
    k_stats<<<tiles, 512>>>(x, W1, adj);   // stats + adj + reduced GEMM1 + gelu
    k_gemm2<<<dim3(8, 4, 16), 256>>>(W2);  // 1024x256, K=512, split-K=16
    k_attn <<<tiles, 512>>>(x, adj, out);
}